// round 1
// baseline (speedup 1.0000x reference)
#include <cuda_runtime.h>
#include <cuda_bf16.h>

#define N_NODES 100000
#define D 128

// Scratch for the SpMM result (allocation-free rule: __device__ global).
__device__ float g_agg[(size_t)N_NODES * D];

// ---------------------------------------------------------------------------
// Kernel 1: zero the aggregation buffer (float4 grid-stride).
// ---------------------------------------------------------------------------
__global__ void zero_agg_kernel() {
    const int n4 = (N_NODES * D) / 4;
    float4* p = reinterpret_cast<float4*>(g_agg);
    const float4 z = make_float4(0.f, 0.f, 0.f, 0.f);
    for (int i = blockIdx.x * blockDim.x + threadIdx.x; i < n4;
         i += gridDim.x * blockDim.x) {
        p[i] = z;
    }
}

// ---------------------------------------------------------------------------
// Kernel 2: SpMM.  agg[r] += val[e] * h[col[e]] for sorted edge_rows.
// One warp per contiguous chunk of CHUNK edges; lane owns 4 features.
// Interior rows of a chunk are flushed with plain float4 stores (exclusively
// owned since rows are sorted); the chunk's first and last rows may be shared
// with neighboring chunks -> atomicAdd.
// ---------------------------------------------------------------------------
#define SPMM_CHUNK 256

__global__ __launch_bounds__(256) void spmm_kernel(
    const int* __restrict__ rows, const int* __restrict__ cols,
    const float* __restrict__ vals, const float* __restrict__ h, int E) {
    const int warp = (blockIdx.x * blockDim.x + threadIdx.x) >> 5;
    const int lane = threadIdx.x & 31;

    long e0 = (long)warp * SPMM_CHUNK;
    if (e0 >= E) return;
    long e1 = e0 + SPMM_CHUNK;
    if (e1 > E) e1 = E;

    const int first = __ldg(&rows[e0]);
    int cur = first;
    float4 acc = make_float4(0.f, 0.f, 0.f, 0.f);

    // Prefetched edge metadata (breaks the col->h dependent chain).
    int r_n = first;
    int c_n = __ldg(&cols[e0]);
    float v_n = __ldg(&vals[e0]);

    for (long e = e0; e < e1; ++e) {
        const int r = r_n;
        const int c = c_n;
        const float v = v_n;
        if (e + 1 < e1) {
            r_n = __ldg(&rows[e + 1]);
            c_n = __ldg(&cols[e + 1]);
            v_n = __ldg(&vals[e + 1]);
        }

        if (r != cur) {
            float* dst = g_agg + (size_t)cur * D + lane * 4;
            if (cur == first) {
                atomicAdd(dst + 0, acc.x);
                atomicAdd(dst + 1, acc.y);
                atomicAdd(dst + 2, acc.z);
                atomicAdd(dst + 3, acc.w);
            } else {
                *reinterpret_cast<float4*>(dst) = acc;
            }
            acc = make_float4(0.f, 0.f, 0.f, 0.f);
            cur = r;
        }

        const float4 hv =
            *reinterpret_cast<const float4*>(h + (size_t)c * D + lane * 4);
        acc.x = fmaf(v, hv.x, acc.x);
        acc.y = fmaf(v, hv.y, acc.y);
        acc.z = fmaf(v, hv.z, acc.z);
        acc.w = fmaf(v, hv.w, acc.w);
    }

    // Last row may continue into the next chunk -> always atomic.
    float* dst = g_agg + (size_t)cur * D + lane * 4;
    atomicAdd(dst + 0, acc.x);
    atomicAdd(dst + 1, acc.y);
    atomicAdd(dst + 2, acc.z);
    atomicAdd(dst + 3, acc.w);
}

// ---------------------------------------------------------------------------
// Kernel 3: out = relu(agg @ W^T + b).
// W is [128,128] row-major; out[i][j] = dot(agg[i,:], W[j,:]) -> both operands
// K-contiguous.  Block = 256 threads computing a 64-row x 128-col tile.
// Each thread: 8 rows x 4 cols accumulators; K chunked by 32 through smem.
// ---------------------------------------------------------------------------
__global__ __launch_bounds__(256) void gemm_bias_relu_kernel(
    const float* __restrict__ W, const float* __restrict__ b,
    float* __restrict__ out) {
    __shared__ float As[64][33];   // agg tile  [row][k]
    __shared__ float Ws[128][33];  // W tile    [j][k]

    const int t = threadIdx.x;
    const int tx = t & 31;        // 0..31  -> column group
    const int ty = t >> 5;        // 0..7   -> row group
    const int row0 = blockIdx.x * 64;

    float acc[8][4];
#pragma unroll
    for (int m = 0; m < 8; ++m)
#pragma unroll
        for (int c = 0; c < 4; ++c) acc[m][c] = 0.f;

    for (int k0 = 0; k0 < D; k0 += 32) {
        // Load agg tile: 64x32 floats, 8 per thread, coalesced in k.
#pragma unroll
        for (int i = 0; i < 8; ++i) {
            const int id = i * 256 + t;
            const int rr = id >> 5;        // 0..63
            const int kk = id & 31;
            const int gr = row0 + rr;
            As[rr][kk] =
                (gr < N_NODES) ? g_agg[(size_t)gr * D + k0 + kk] : 0.f;
        }
        // Load W tile: 128x32 floats, 16 per thread, coalesced in k.
#pragma unroll
        for (int i = 0; i < 16; ++i) {
            const int id = i * 256 + t;
            const int jj = id >> 5;        // 0..127
            const int kk = id & 31;
            Ws[jj][kk] = W[jj * D + k0 + kk];
        }
        __syncthreads();

#pragma unroll
        for (int kk = 0; kk < 32; ++kk) {
            float a[8], w[4];
#pragma unroll
            for (int m = 0; m < 8; ++m) a[m] = As[ty * 8 + m][kk];
#pragma unroll
            for (int c = 0; c < 4; ++c) w[c] = Ws[tx + 32 * c][kk];
#pragma unroll
            for (int m = 0; m < 8; ++m)
#pragma unroll
                for (int c = 0; c < 4; ++c)
                    acc[m][c] = fmaf(a[m], w[c], acc[m][c]);
        }
        __syncthreads();
    }

    // Epilogue: bias + relu + store.
    float bb[4];
#pragma unroll
    for (int c = 0; c < 4; ++c) bb[c] = __ldg(&b[tx + 32 * c]);

#pragma unroll
    for (int m = 0; m < 8; ++m) {
        const int gr = row0 + ty * 8 + m;
        if (gr < N_NODES) {
#pragma unroll
            for (int c = 0; c < 4; ++c) {
                const float v = acc[m][c] + bb[c];
                out[(size_t)gr * D + tx + 32 * c] = v > 0.f ? v : 0.f;
            }
        }
    }
}

// ---------------------------------------------------------------------------
// Launch
// ---------------------------------------------------------------------------
extern "C" void kernel_launch(void* const* d_in, const int* in_sizes, int n_in,
                              void* d_out, int out_size) {
    const int* edge_rows = (const int*)d_in[0];
    const int* edge_cols = (const int*)d_in[1];
    const float* edge_vals = (const float*)d_in[2];
    const float* h = (const float*)d_in[3];
    const float* W = (const float*)d_in[4];
    const float* b = (const float*)d_in[5];
    float* out = (float*)d_out;

    const int E = in_sizes[0];

    // 1) zero agg
    zero_agg_kernel<<<2048, 256>>>();

    // 2) SpMM
    const int nwarps = (E + SPMM_CHUNK - 1) / SPMM_CHUNK;
    const int blocks = (nwarps * 32 + 255) / 256;
    spmm_kernel<<<blocks, 256>>>(edge_rows, edge_cols, edge_vals, h, E);

    // 3) GEMM + bias + relu
    const int gblocks = (N_NODES + 63) / 64;
    gemm_bias_relu_kernel<<<gblocks, 256>>>(W, b, out);
}

// round 2
// speedup vs baseline: 1.5216x; 1.5216x over previous
#include <cuda_runtime.h>
#include <cuda_bf16.h>
#include <cstdint>

#define N_NODES 100000
#define D 128

// Scratch for the SpMM result (allocation-free rule: __device__ global).
__device__ float g_agg[(size_t)N_NODES * D];

// ---------------------------------------------------------------------------
// Kernel 1: zero the aggregation buffer (float4 grid-stride).
// ---------------------------------------------------------------------------
__global__ void zero_agg_kernel() {
    const int n4 = (N_NODES * D) / 4;
    float4* p = reinterpret_cast<float4*>(g_agg);
    const float4 z = make_float4(0.f, 0.f, 0.f, 0.f);
    for (int i = blockIdx.x * blockDim.x + threadIdx.x; i < n4;
         i += gridDim.x * blockDim.x) {
        p[i] = z;
    }
}

// ---------------------------------------------------------------------------
// Kernel 2: SpMM.  agg[r] += val[e] * h[col[e]] for sorted edge_rows.
// One warp per contiguous chunk of SPMM_CHUNK edges; lane owns 4 features.
// Edge metadata loaded 4-at-a-time (vectorized, lane-uniform broadcast);
// the 4 h-row gathers are issued up front for MLP=4.
// Interior rows flushed with plain float4 stores (exclusively owned, rows
// sorted); chunk-boundary rows use atomicAdd.
// ---------------------------------------------------------------------------
#define SPMM_CHUNK 256

__global__ __launch_bounds__(256) void spmm_kernel(
    const int* __restrict__ rows, const int* __restrict__ cols,
    const float* __restrict__ vals, const float* __restrict__ h, int E) {
    const int warp = (blockIdx.x * blockDim.x + threadIdx.x) >> 5;
    const int lane = threadIdx.x & 31;

    int e0 = warp * SPMM_CHUNK;
    if (e0 >= E) return;
    int e1 = e0 + SPMM_CHUNK;
    if (e1 > E) e1 = E;

    const int first = __ldg(&rows[e0]);
    int cur = first;
    float4 acc = make_float4(0.f, 0.f, 0.f, 0.f);
    const int fo = lane * 4;  // feature offset for this lane

    // main loop: groups of 4 edges (e0 is 4-aligned)
    int e = e0;
    const int e1v = e0 + ((e1 - e0) & ~3);
    for (; e < e1v; e += 4) {
        const int4 r4 = *reinterpret_cast<const int4*>(rows + e);
        const int4 c4 = *reinterpret_cast<const int4*>(cols + e);
        const float4 v4 = *reinterpret_cast<const float4*>(vals + e);

        // issue all 4 gathers first (independent -> MLP=4)
        const float4 hv0 = *reinterpret_cast<const float4*>(h + (size_t)c4.x * D + fo);
        const float4 hv1 = *reinterpret_cast<const float4*>(h + (size_t)c4.y * D + fo);
        const float4 hv2 = *reinterpret_cast<const float4*>(h + (size_t)c4.z * D + fo);
        const float4 hv3 = *reinterpret_cast<const float4*>(h + (size_t)c4.w * D + fo);

        const int rr[4] = {r4.x, r4.y, r4.z, r4.w};
        const float vv[4] = {v4.x, v4.y, v4.z, v4.w};
        const float4 hh[4] = {hv0, hv1, hv2, hv3};

#pragma unroll
        for (int j = 0; j < 4; ++j) {
            const int r = rr[j];
            if (r != cur) {
                float* dst = g_agg + (size_t)cur * D + fo;
                if (cur == first) {
                    atomicAdd(dst + 0, acc.x);
                    atomicAdd(dst + 1, acc.y);
                    atomicAdd(dst + 2, acc.z);
                    atomicAdd(dst + 3, acc.w);
                } else {
                    *reinterpret_cast<float4*>(dst) = acc;
                }
                acc = make_float4(0.f, 0.f, 0.f, 0.f);
                cur = r;
            }
            const float v = vv[j];
            acc.x = fmaf(v, hh[j].x, acc.x);
            acc.y = fmaf(v, hh[j].y, acc.y);
            acc.z = fmaf(v, hh[j].z, acc.z);
            acc.w = fmaf(v, hh[j].w, acc.w);
        }
    }
    // scalar tail (only if E not multiple of 4 within last chunk)
    for (; e < e1; ++e) {
        const int r = __ldg(&rows[e]);
        if (r != cur) {
            float* dst = g_agg + (size_t)cur * D + fo;
            if (cur == first) {
                atomicAdd(dst + 0, acc.x);
                atomicAdd(dst + 1, acc.y);
                atomicAdd(dst + 2, acc.z);
                atomicAdd(dst + 3, acc.w);
            } else {
                *reinterpret_cast<float4*>(dst) = acc;
            }
            acc = make_float4(0.f, 0.f, 0.f, 0.f);
            cur = r;
        }
        const float v = __ldg(&vals[e]);
        const float4 hv = *reinterpret_cast<const float4*>(h + (size_t)__ldg(&cols[e]) * D + fo);
        acc.x = fmaf(v, hv.x, acc.x);
        acc.y = fmaf(v, hv.y, acc.y);
        acc.z = fmaf(v, hv.z, acc.z);
        acc.w = fmaf(v, hv.w, acc.w);
    }

    // Last row may continue into the next chunk -> always atomic.
    float* dst = g_agg + (size_t)cur * D + fo;
    atomicAdd(dst + 0, acc.x);
    atomicAdd(dst + 1, acc.y);
    atomicAdd(dst + 2, acc.z);
    atomicAdd(dst + 3, acc.w);
}

// ---------------------------------------------------------------------------
// Kernel 3: out = relu(agg @ W^T + b) via split-bf16 tensor cores.
// a = a_hi + a_lo (bf16 each); D = Ahi*Bhi + Ahi*Blo + Alo*Bhi  (fp32 acc),
// dropped Alo*Blo term ~2^-18 relative -> total rel err ~1e-5.
// Block: 256 threads (8 warps), tile 128 rows x 128 cols, K=128 in one shot.
// Warp layout: 4 (m) x 2 (n) -> warp tile 32m x 64n.
// ---------------------------------------------------------------------------
#define GEMM_SMEM_BYTES (4 * 128 * 256)  // Ahi, Alo, Whi, Wlo : 32KB each

// swizzled byte offset inside a [128 rows][128 bf16] tile (256B rows)
__device__ __forceinline__ int swz(int row, int col /*bf16 units*/) {
    return row * 256 + (((col * 2) ^ ((row & 7) << 4)));
}

__device__ __forceinline__ uint32_t smem_u32(const void* p) {
    return (uint32_t)__cvta_generic_to_shared(p);
}

__device__ __forceinline__ void ldsm_x4(uint32_t& r0, uint32_t& r1,
                                        uint32_t& r2, uint32_t& r3,
                                        uint32_t addr) {
    asm volatile(
        "ldmatrix.sync.aligned.m8n8.x4.shared.b16 {%0,%1,%2,%3}, [%4];"
        : "=r"(r0), "=r"(r1), "=r"(r2), "=r"(r3)
        : "r"(addr));
}

__device__ __forceinline__ void ldsm_x2(uint32_t& r0, uint32_t& r1,
                                        uint32_t addr) {
    asm volatile(
        "ldmatrix.sync.aligned.m8n8.x2.shared.b16 {%0,%1}, [%2];"
        : "=r"(r0), "=r"(r1)
        : "r"(addr));
}

__device__ __forceinline__ void mma_bf16(float* c, const uint32_t* a,
                                         const uint32_t* b) {
    asm volatile(
        "mma.sync.aligned.m16n8k16.row.col.f32.bf16.bf16.f32 "
        "{%0,%1,%2,%3}, {%4,%5,%6,%7}, {%8,%9}, {%0,%1,%2,%3};"
        : "+f"(c[0]), "+f"(c[1]), "+f"(c[2]), "+f"(c[3])
        : "r"(a[0]), "r"(a[1]), "r"(a[2]), "r"(a[3]), "r"(b[0]), "r"(b[1]));
}

__device__ __forceinline__ uint32_t pack_bf16(float hi_a, float hi_b) {
    __nv_bfloat162 p = __floats2bfloat162_rn(hi_a, hi_b);
    return *reinterpret_cast<uint32_t*>(&p);
}

__global__ __launch_bounds__(256) void gemm_bias_relu_tc(
    const float* __restrict__ W, const float* __restrict__ b,
    float* __restrict__ out) {
    extern __shared__ char smem[];
    __nv_bfloat16* Ahi = reinterpret_cast<__nv_bfloat16*>(smem);
    __nv_bfloat16* Alo = reinterpret_cast<__nv_bfloat16*>(smem + 32768);
    __nv_bfloat16* Whi = reinterpret_cast<__nv_bfloat16*>(smem + 65536);
    __nv_bfloat16* Wlo = reinterpret_cast<__nv_bfloat16*>(smem + 98304);

    const int t = threadIdx.x;
    const int lane = t & 31;
    const int warp = t >> 5;
    const int row0 = blockIdx.x * 128;

    // ---- load + split-convert A (agg) tile: 128x128 fp32, 16 float4/thread
    {
        const char* Ahi_b = reinterpret_cast<const char*>(Ahi);
        const char* Alo_b = reinterpret_cast<const char*>(Alo);
#pragma unroll
        for (int i = 0; i < 16; ++i) {
            const int idx = i * 256 + t;
            const int r = idx >> 5;          // 0..127
            const int c4 = idx & 31;         // float4 index
            const int gr = row0 + r;
            float4 a;
            if (gr < N_NODES)
                a = *reinterpret_cast<const float4*>(g_agg + (size_t)gr * D + c4 * 4);
            else
                a = make_float4(0.f, 0.f, 0.f, 0.f);
            float h0 = __bfloat162float(__float2bfloat16(a.x));
            float h1 = __bfloat162float(__float2bfloat16(a.y));
            float h2 = __bfloat162float(__float2bfloat16(a.z));
            float h3 = __bfloat162float(__float2bfloat16(a.w));
            uint2 uh = make_uint2(pack_bf16(a.x, a.y), pack_bf16(a.z, a.w));
            uint2 ul = make_uint2(pack_bf16(a.x - h0, a.y - h1),
                                  pack_bf16(a.z - h2, a.w - h3));
            const int off = swz(r, c4 * 4);
            *reinterpret_cast<uint2*>(const_cast<char*>(Ahi_b) + off) = uh;
            *reinterpret_cast<uint2*>(const_cast<char*>(Alo_b) + off) = ul;
        }
    }
    // ---- load + split-convert W tile: 128x128 fp32, 16 float4/thread
    {
        char* Whi_b = reinterpret_cast<char*>(Whi);
        char* Wlo_b = reinterpret_cast<char*>(Wlo);
#pragma unroll
        for (int i = 0; i < 16; ++i) {
            const int idx = i * 256 + t;
            const int r = idx >> 5;
            const int c4 = idx & 31;
            float4 a = *reinterpret_cast<const float4*>(W + r * D + c4 * 4);
            float h0 = __bfloat162float(__float2bfloat16(a.x));
            float h1 = __bfloat162float(__float2bfloat16(a.y));
            float h2 = __bfloat162float(__float2bfloat16(a.z));
            float h3 = __bfloat162float(__float2bfloat16(a.w));
            uint2 uh = make_uint2(pack_bf16(a.x, a.y), pack_bf16(a.z, a.w));
            uint2 ul = make_uint2(pack_bf16(a.x - h0, a.y - h1),
                                  pack_bf16(a.z - h2, a.w - h3));
            const int off = swz(r, c4 * 4);
            *reinterpret_cast<uint2*>(Whi_b + off) = uh;
            *reinterpret_cast<uint2*>(Wlo_b + off) = ul;
        }
    }
    __syncthreads();

    // warp tile: 32 m x 64 n;  warps: 4(m) x 2(n)
    const int wm0 = (warp & 3) * 32;
    const int wn0 = (warp >> 2) * 64;

    float c[2][8][4];
#pragma unroll
    for (int mt = 0; mt < 2; ++mt)
#pragma unroll
        for (int nt = 0; nt < 8; ++nt)
#pragma unroll
            for (int k = 0; k < 4; ++k) c[mt][nt][k] = 0.f;

    const uint32_t Ahi_s = smem_u32(Ahi);
    const uint32_t Alo_s = smem_u32(Alo);
    const uint32_t Whi_s = smem_u32(Whi);
    const uint32_t Wlo_s = smem_u32(Wlo);

    // ldmatrix lane addressing
    const int a_row_l = lane & 15;          // row within 16-row tile
    const int a_koff = (lane >> 4) * 8;     // k half
    const int b_row_l = lane & 7;           // n within 8
    const int b_koff = ((lane >> 3) & 1) * 8;

#pragma unroll
    for (int ks = 0; ks < 8; ++ks) {
        const int k0 = ks * 16;
        uint32_t ahi[2][4], alo[2][4];
#pragma unroll
        for (int mt = 0; mt < 2; ++mt) {
            const int r = wm0 + mt * 16 + a_row_l;
            const int off = swz(r, k0 + a_koff);
            ldsm_x4(ahi[mt][0], ahi[mt][1], ahi[mt][2], ahi[mt][3], Ahi_s + off);
            ldsm_x4(alo[mt][0], alo[mt][1], alo[mt][2], alo[mt][3], Alo_s + off);
        }
#pragma unroll
        for (int nt = 0; nt < 8; ++nt) {
            const int nr = wn0 + nt * 8 + b_row_l;
            const int off = swz(nr, k0 + b_koff);
            uint32_t bhi[2], blo[2];
            ldsm_x2(bhi[0], bhi[1], Whi_s + off);
            ldsm_x2(blo[0], blo[1], Wlo_s + off);
#pragma unroll
            for (int mt = 0; mt < 2; ++mt) {
                mma_bf16(c[mt][nt], ahi[mt], bhi);
                mma_bf16(c[mt][nt], ahi[mt], blo);
                mma_bf16(c[mt][nt], alo[mt], bhi);
            }
        }
    }

    // ---- epilogue: bias + relu + store (float2 per frag half)
    const int qn = 2 * (lane & 3);  // col pair base within 8
    const int qr = lane >> 2;       // row within 8
    float2 bb[8];
#pragma unroll
    for (int nt = 0; nt < 8; ++nt) {
        const int n = wn0 + nt * 8 + qn;
        bb[nt] = make_float2(__ldg(&b[n]), __ldg(&b[n + 1]));
    }
#pragma unroll
    for (int mt = 0; mt < 2; ++mt) {
        const int r_lo = row0 + wm0 + mt * 16 + qr;
        const int r_hi = r_lo + 8;
#pragma unroll
        for (int nt = 0; nt < 8; ++nt) {
            const int n = wn0 + nt * 8 + qn;
            if (r_lo < N_NODES) {
                float2 v;
                v.x = fmaxf(c[mt][nt][0] + bb[nt].x, 0.f);
                v.y = fmaxf(c[mt][nt][1] + bb[nt].y, 0.f);
                *reinterpret_cast<float2*>(out + (size_t)r_lo * D + n) = v;
            }
            if (r_hi < N_NODES) {
                float2 v;
                v.x = fmaxf(c[mt][nt][2] + bb[nt].x, 0.f);
                v.y = fmaxf(c[mt][nt][3] + bb[nt].y, 0.f);
                *reinterpret_cast<float2*>(out + (size_t)r_hi * D + n) = v;
            }
        }
    }
}

// ---------------------------------------------------------------------------
// Launch
// ---------------------------------------------------------------------------
extern "C" void kernel_launch(void* const* d_in, const int* in_sizes, int n_in,
                              void* d_out, int out_size) {
    const int* edge_rows = (const int*)d_in[0];
    const int* edge_cols = (const int*)d_in[1];
    const float* edge_vals = (const float*)d_in[2];
    const float* h = (const float*)d_in[3];
    const float* W = (const float*)d_in[4];
    const float* b = (const float*)d_in[5];
    float* out = (float*)d_out;

    const int E = in_sizes[0];

    static bool smem_set = false;
    if (!smem_set) {
        cudaFuncSetAttribute(gemm_bias_relu_tc,
                             cudaFuncAttributeMaxDynamicSharedMemorySize,
                             GEMM_SMEM_BYTES);
        smem_set = true;
    }

    // 1) zero agg
    zero_agg_kernel<<<2048, 256>>>();

    // 2) SpMM
    const int nwarps = (E + SPMM_CHUNK - 1) / SPMM_CHUNK;
    const int blocks = (nwarps * 32 + 255) / 256;
    spmm_kernel<<<blocks, 256>>>(edge_rows, edge_cols, edge_vals, h, E);

    // 3) GEMM + bias + relu (tensor cores, split bf16)
    const int gblocks = (N_NODES + 127) / 128;
    gemm_bias_relu_tc<<<gblocks, 256, GEMM_SMEM_BYTES>>>(W, b, out);
}

// round 3
// speedup vs baseline: 1.7044x; 1.1201x over previous
#include <cuda_runtime.h>
#include <cuda_fp16.h>
#include <cuda_bf16.h>
#include <cstdint>

#define N_NODES 100000
#define D 128
#define SPMM_CHUNK 256
#define MAX_SLOTS 32768   // >= 2 * ceil(E / SPMM_CHUNK)

// Scratch (allocation-free rule: __device__ globals).
__device__ __half g_ht[(size_t)N_NODES * D];          // h @ W^T in fp16
__device__ float  g_bnd_val[(size_t)MAX_SLOTS * D];   // boundary partials
__device__ int    g_bnd_row[MAX_SLOTS];               // boundary row ids

// ---------------------------------------------------------------------------
// Kernel 1: prefill out[i][:] = relu(b) for every row (covers empty rows and
// un-poisons d_out; SpMM/epilogue overwrite every touched row).
// ---------------------------------------------------------------------------
__global__ __launch_bounds__(256) void prefill_kernel(
    const float* __restrict__ b, float* __restrict__ out) {
    __shared__ float rb[D];
    if (threadIdx.x < D) rb[threadIdx.x] = fmaxf(b[threadIdx.x], 0.f);
    __syncthreads();
    const int n4 = N_NODES * (D / 4);
    float4* o4 = reinterpret_cast<float4*>(out);
    for (int i = blockIdx.x * blockDim.x + threadIdx.x; i < n4;
         i += gridDim.x * blockDim.x) {
        const int c4 = i & 31;
        o4[i] = make_float4(rb[c4 * 4], rb[c4 * 4 + 1], rb[c4 * 4 + 2],
                            rb[c4 * 4 + 3]);
    }
}

// ---------------------------------------------------------------------------
// Kernel 2: h' = h @ W^T, split-bf16 tensor cores, fp16 output.
// ---------------------------------------------------------------------------
#define GEMM_SMEM_BYTES (4 * 128 * 256)  // Ahi, Alo, Whi, Wlo : 32KB each

__device__ __forceinline__ int swz(int row, int col /*bf16 units*/) {
    return row * 256 + (((col * 2) ^ ((row & 7) << 4)));
}
__device__ __forceinline__ uint32_t smem_u32(const void* p) {
    return (uint32_t)__cvta_generic_to_shared(p);
}
__device__ __forceinline__ void ldsm_x4(uint32_t& r0, uint32_t& r1,
                                        uint32_t& r2, uint32_t& r3,
                                        uint32_t addr) {
    asm volatile(
        "ldmatrix.sync.aligned.m8n8.x4.shared.b16 {%0,%1,%2,%3}, [%4];"
        : "=r"(r0), "=r"(r1), "=r"(r2), "=r"(r3)
        : "r"(addr));
}
__device__ __forceinline__ void ldsm_x2(uint32_t& r0, uint32_t& r1,
                                        uint32_t addr) {
    asm volatile(
        "ldmatrix.sync.aligned.m8n8.x2.shared.b16 {%0,%1}, [%2];"
        : "=r"(r0), "=r"(r1)
        : "r"(addr));
}
__device__ __forceinline__ void mma_bf16(float* c, const uint32_t* a,
                                         const uint32_t* b) {
    asm volatile(
        "mma.sync.aligned.m16n8k16.row.col.f32.bf16.bf16.f32 "
        "{%0,%1,%2,%3}, {%4,%5,%6,%7}, {%8,%9}, {%0,%1,%2,%3};"
        : "+f"(c[0]), "+f"(c[1]), "+f"(c[2]), "+f"(c[3])
        : "r"(a[0]), "r"(a[1]), "r"(a[2]), "r"(a[3]), "r"(b[0]), "r"(b[1]));
}
__device__ __forceinline__ uint32_t pack_bf16(float a, float b) {
    __nv_bfloat162 p = __floats2bfloat162_rn(a, b);
    return *reinterpret_cast<uint32_t*>(&p);
}

__global__ __launch_bounds__(256) void transform_tc(
    const float* __restrict__ hin, const float* __restrict__ W) {
    extern __shared__ char smem[];
    char* Ahi_b = smem;
    char* Alo_b = smem + 32768;
    char* Whi_b = smem + 65536;
    char* Wlo_b = smem + 98304;

    const int t = threadIdx.x;
    const int lane = t & 31;
    const int warp = t >> 5;
    const int row0 = blockIdx.x * 128;

#pragma unroll
    for (int i = 0; i < 16; ++i) {
        const int idx = i * 256 + t;
        const int r = idx >> 5;
        const int c4 = idx & 31;
        const int gr = row0 + r;
        float4 a = (gr < N_NODES)
                       ? *reinterpret_cast<const float4*>(hin + (size_t)gr * D + c4 * 4)
                       : make_float4(0.f, 0.f, 0.f, 0.f);
        float h0 = __bfloat162float(__float2bfloat16(a.x));
        float h1 = __bfloat162float(__float2bfloat16(a.y));
        float h2 = __bfloat162float(__float2bfloat16(a.z));
        float h3 = __bfloat162float(__float2bfloat16(a.w));
        const int off = swz(r, c4 * 4);
        *reinterpret_cast<uint2*>(Ahi_b + off) =
            make_uint2(pack_bf16(a.x, a.y), pack_bf16(a.z, a.w));
        *reinterpret_cast<uint2*>(Alo_b + off) =
            make_uint2(pack_bf16(a.x - h0, a.y - h1), pack_bf16(a.z - h2, a.w - h3));
    }
#pragma unroll
    for (int i = 0; i < 16; ++i) {
        const int idx = i * 256 + t;
        const int r = idx >> 5;
        const int c4 = idx & 31;
        float4 a = *reinterpret_cast<const float4*>(W + r * D + c4 * 4);
        float h0 = __bfloat162float(__float2bfloat16(a.x));
        float h1 = __bfloat162float(__float2bfloat16(a.y));
        float h2 = __bfloat162float(__float2bfloat16(a.z));
        float h3 = __bfloat162float(__float2bfloat16(a.w));
        const int off = swz(r, c4 * 4);
        *reinterpret_cast<uint2*>(Whi_b + off) =
            make_uint2(pack_bf16(a.x, a.y), pack_bf16(a.z, a.w));
        *reinterpret_cast<uint2*>(Wlo_b + off) =
            make_uint2(pack_bf16(a.x - h0, a.y - h1), pack_bf16(a.z - h2, a.w - h3));
    }
    __syncthreads();

    const int wm0 = (warp & 3) * 32;
    const int wn0 = (warp >> 2) * 64;

    float c[2][8][4];
#pragma unroll
    for (int mt = 0; mt < 2; ++mt)
#pragma unroll
        for (int nt = 0; nt < 8; ++nt)
#pragma unroll
            for (int k = 0; k < 4; ++k) c[mt][nt][k] = 0.f;

    const uint32_t Ahi_s = smem_u32(Ahi_b);
    const uint32_t Alo_s = smem_u32(Alo_b);
    const uint32_t Whi_s = smem_u32(Whi_b);
    const uint32_t Wlo_s = smem_u32(Wlo_b);

    const int a_row_l = lane & 15;
    const int a_koff = (lane >> 4) * 8;
    const int b_row_l = lane & 7;
    const int b_koff = ((lane >> 3) & 1) * 8;

#pragma unroll
    for (int ks = 0; ks < 8; ++ks) {
        const int k0 = ks * 16;
        uint32_t ahi[2][4], alo[2][4];
#pragma unroll
        for (int mt = 0; mt < 2; ++mt) {
            const int off = swz(wm0 + mt * 16 + a_row_l, k0 + a_koff);
            ldsm_x4(ahi[mt][0], ahi[mt][1], ahi[mt][2], ahi[mt][3], Ahi_s + off);
            ldsm_x4(alo[mt][0], alo[mt][1], alo[mt][2], alo[mt][3], Alo_s + off);
        }
#pragma unroll
        for (int nt = 0; nt < 8; ++nt) {
            const int off = swz(wn0 + nt * 8 + b_row_l, k0 + b_koff);
            uint32_t bhi[2], blo[2];
            ldsm_x2(bhi[0], bhi[1], Whi_s + off);
            ldsm_x2(blo[0], blo[1], Wlo_s + off);
#pragma unroll
            for (int mt = 0; mt < 2; ++mt) {
                mma_bf16(c[mt][nt], ahi[mt], bhi);
                mma_bf16(c[mt][nt], ahi[mt], blo);
                mma_bf16(c[mt][nt], alo[mt], bhi);
            }
        }
    }

    // epilogue: fp16 store (no bias/relu here)
    const int qn = 2 * (lane & 3);
    const int qr = lane >> 2;
#pragma unroll
    for (int mt = 0; mt < 2; ++mt) {
        const int r_lo = row0 + wm0 + mt * 16 + qr;
        const int r_hi = r_lo + 8;
#pragma unroll
        for (int nt = 0; nt < 8; ++nt) {
            const int n = wn0 + nt * 8 + qn;
            if (r_lo < N_NODES)
                *reinterpret_cast<__half2*>(g_ht + (size_t)r_lo * D + n) =
                    __floats2half2_rn(c[mt][nt][0], c[mt][nt][1]);
            if (r_hi < N_NODES)
                *reinterpret_cast<__half2*>(g_ht + (size_t)r_hi * D + n) =
                    __floats2half2_rn(c[mt][nt][2], c[mt][nt][3]);
        }
    }
}

// ---------------------------------------------------------------------------
// Kernel 3: SpMM over fp16 h'.  out[r] = relu(sum v*h'[col] + b) for rows
// wholly owned by a warp chunk; chunk-boundary partials -> scratch slots.
// ---------------------------------------------------------------------------
__global__ __launch_bounds__(256) void spmm_fp16_kernel(
    const int* __restrict__ rows, const int* __restrict__ cols,
    const float* __restrict__ vals, const float* __restrict__ b,
    float* __restrict__ out, int E) {
    const int warp = (blockIdx.x * blockDim.x + threadIdx.x) >> 5;
    const int lane = threadIdx.x & 31;

    const int e0 = warp * SPMM_CHUNK;
    if (e0 >= E) return;
    int e1 = e0 + SPMM_CHUNK;
    if (e1 > E) e1 = E;

    const int fo = lane * 4;  // feature offset (4 features / lane)
    const float4 bb = *reinterpret_cast<const float4*>(b + fo);
    const int slot0 = warp * 2;

    int cur = __ldg(&rows[e0]);
    bool firstDone = false;
    float4 acc = make_float4(0.f, 0.f, 0.f, 0.f);

    int e = e0;
    const int e1v = e0 + ((e1 - e0) & ~3);
    for (; e < e1v; e += 4) {
        const int4 r4 = *reinterpret_cast<const int4*>(rows + e);
        const int4 c4 = *reinterpret_cast<const int4*>(cols + e);
        const float4 v4 = *reinterpret_cast<const float4*>(vals + e);

        // issue the 4 fp16 gathers first (MLP=4)
        const uint2 u0 = *reinterpret_cast<const uint2*>(g_ht + (size_t)c4.x * D + fo);
        const uint2 u1 = *reinterpret_cast<const uint2*>(g_ht + (size_t)c4.y * D + fo);
        const uint2 u2 = *reinterpret_cast<const uint2*>(g_ht + (size_t)c4.z * D + fo);
        const uint2 u3 = *reinterpret_cast<const uint2*>(g_ht + (size_t)c4.w * D + fo);

        const int rr[4] = {r4.x, r4.y, r4.z, r4.w};
        const float vv[4] = {v4.x, v4.y, v4.z, v4.w};
        const uint2 uu[4] = {u0, u1, u2, u3};

#pragma unroll
        for (int j = 0; j < 4; ++j) {
            const int r = rr[j];
            if (r != cur) {
                if (!firstDone) {
                    *reinterpret_cast<float4*>(g_bnd_val + (size_t)slot0 * D + fo) = acc;
                    if (lane == 0) g_bnd_row[slot0] = cur;
                    firstDone = true;
                } else {
                    float4 o;
                    o.x = fmaxf(acc.x + bb.x, 0.f);
                    o.y = fmaxf(acc.y + bb.y, 0.f);
                    o.z = fmaxf(acc.z + bb.z, 0.f);
                    o.w = fmaxf(acc.w + bb.w, 0.f);
                    *reinterpret_cast<float4*>(out + (size_t)cur * D + fo) = o;
                }
                acc = make_float4(0.f, 0.f, 0.f, 0.f);
                cur = r;
            }
            const __half2 h01 = reinterpret_cast<const __half2*>(&uu[j])[0];
            const __half2 h23 = reinterpret_cast<const __half2*>(&uu[j])[1];
            const float2 f01 = __half22float2(h01);
            const float2 f23 = __half22float2(h23);
            const float v = vv[j];
            acc.x = fmaf(v, f01.x, acc.x);
            acc.y = fmaf(v, f01.y, acc.y);
            acc.z = fmaf(v, f23.x, acc.z);
            acc.w = fmaf(v, f23.y, acc.w);
        }
    }
    for (; e < e1; ++e) {
        const int r = __ldg(&rows[e]);
        if (r != cur) {
            if (!firstDone) {
                *reinterpret_cast<float4*>(g_bnd_val + (size_t)slot0 * D + fo) = acc;
                if (lane == 0) g_bnd_row[slot0] = cur;
                firstDone = true;
            } else {
                float4 o;
                o.x = fmaxf(acc.x + bb.x, 0.f);
                o.y = fmaxf(acc.y + bb.y, 0.f);
                o.z = fmaxf(acc.z + bb.z, 0.f);
                o.w = fmaxf(acc.w + bb.w, 0.f);
                *reinterpret_cast<float4*>(out + (size_t)cur * D + fo) = o;
            }
            acc = make_float4(0.f, 0.f, 0.f, 0.f);
            cur = r;
        }
        const uint2 u = *reinterpret_cast<const uint2*>(
            g_ht + (size_t)__ldg(&cols[e]) * D + fo);
        const __half2 h01 = reinterpret_cast<const __half2*>(&u)[0];
        const __half2 h23 = reinterpret_cast<const __half2*>(&u)[1];
        const float2 f01 = __half22float2(h01);
        const float2 f23 = __half22float2(h23);
        const float v = __ldg(&vals[e]);
        acc.x = fmaf(v, f01.x, acc.x);
        acc.y = fmaf(v, f01.y, acc.y);
        acc.z = fmaf(v, f23.x, acc.z);
        acc.w = fmaf(v, f23.y, acc.w);
    }

    // final row of the chunk -> scratch (may continue into next chunk)
    if (!firstDone) {
        // chunk was a single row: fill both slots (second = zero contribution)
        *reinterpret_cast<float4*>(g_bnd_val + (size_t)slot0 * D + fo) = acc;
        *reinterpret_cast<float4*>(g_bnd_val + (size_t)(slot0 + 1) * D + fo) =
            make_float4(0.f, 0.f, 0.f, 0.f);
        if (lane == 0) {
            g_bnd_row[slot0] = cur;
            g_bnd_row[slot0 + 1] = cur;
        }
    } else {
        *reinterpret_cast<float4*>(g_bnd_val + (size_t)(slot0 + 1) * D + fo) = acc;
        if (lane == 0) g_bnd_row[slot0 + 1] = cur;
    }
}

// ---------------------------------------------------------------------------
// Kernel 4: segmented combine of boundary slots -> relu(sum + b) -> out.
// Slot rows are monotone nondecreasing (chunks follow sorted edge order).
// ---------------------------------------------------------------------------
__global__ __launch_bounds__(256) void boundary_epilogue(
    const float* __restrict__ b, float* __restrict__ out, int nslots) {
    const int warp = (blockIdx.x * blockDim.x + threadIdx.x) >> 5;
    const int lane = threadIdx.x & 31;
    if (warp >= nslots) return;

    const int r = __ldg(&g_bnd_row[warp]);
    if (warp > 0 && __ldg(&g_bnd_row[warp - 1]) == r) return;  // not head

    const int fo = lane * 4;
    float4 sum = *reinterpret_cast<const float4*>(g_bnd_val + (size_t)warp * D + fo);
    for (int t = warp + 1; t < nslots && __ldg(&g_bnd_row[t]) == r; ++t) {
        const float4 v =
            *reinterpret_cast<const float4*>(g_bnd_val + (size_t)t * D + fo);
        sum.x += v.x; sum.y += v.y; sum.z += v.z; sum.w += v.w;
    }
    const float4 bb = *reinterpret_cast<const float4*>(b + fo);
    float4 o;
    o.x = fmaxf(sum.x + bb.x, 0.f);
    o.y = fmaxf(sum.y + bb.y, 0.f);
    o.z = fmaxf(sum.z + bb.z, 0.f);
    o.w = fmaxf(sum.w + bb.w, 0.f);
    *reinterpret_cast<float4*>(out + (size_t)r * D + fo) = o;
}

// ---------------------------------------------------------------------------
// Launch
// ---------------------------------------------------------------------------
extern "C" void kernel_launch(void* const* d_in, const int* in_sizes, int n_in,
                              void* d_out, int out_size) {
    const int* edge_rows = (const int*)d_in[0];
    const int* edge_cols = (const int*)d_in[1];
    const float* edge_vals = (const float*)d_in[2];
    const float* h = (const float*)d_in[3];
    const float* W = (const float*)d_in[4];
    const float* b = (const float*)d_in[5];
    float* out = (float*)d_out;

    const int E = in_sizes[0];
    const int nchunks = (E + SPMM_CHUNK - 1) / SPMM_CHUNK;
    const int nslots = nchunks * 2;

    static bool smem_set = false;
    if (!smem_set) {
        cudaFuncSetAttribute(transform_tc,
                             cudaFuncAttributeMaxDynamicSharedMemorySize,
                             GEMM_SMEM_BYTES);
        smem_set = true;
    }

    // 1) out = relu(b) everywhere (covers empty rows, un-poisons d_out)
    prefill_kernel<<<2048, 256>>>(b, out);

    // 2) h' = h @ W^T  (fp16)
    transform_tc<<<(N_NODES + 127) / 128, 256, GEMM_SMEM_BYTES>>>(h, W);

    // 3) SpMM over fp16 h'
    const int sblocks = (nchunks * 32 + 255) / 256;
    spmm_fp16_kernel<<<sblocks, 256>>>(edge_rows, edge_cols, edge_vals, b, out, E);

    // 4) combine chunk-boundary partials
    const int eblocks = (nslots * 32 + 255) / 256;
    boundary_epilogue<<<eblocks, 256>>>(b, out, nslots);
}

// round 4
// speedup vs baseline: 1.7740x; 1.0408x over previous
#include <cuda_runtime.h>
#include <cuda_fp16.h>
#include <cuda_bf16.h>
#include <cstdint>

#define N_NODES 100000
#define D 128

// Scratch (allocation-free rule: __device__ globals).
__device__ __half g_ht[(size_t)N_NODES * D];   // h @ W^T in fp16
__device__ int g_row_ptr[N_NODES + 2];         // CSR row pointers

// ---------------------------------------------------------------------------
// Kernel 1: build row_ptr from sorted edge_rows.
// row_ptr[r] = first edge index with rows[e] >= r;  row_ptr[N_NODES] = E.
// Each transition rows[e-1] -> rows[e] fills the gap; every entry written once.
// ---------------------------------------------------------------------------
__global__ __launch_bounds__(256) void rowptr_build(const int* __restrict__ rows,
                                                    int E) {
    const int tid = blockIdx.x * blockDim.x + threadIdx.x;
    const int ngroups = E >> 2;
    for (int g = tid; g < ngroups; g += gridDim.x * blockDim.x) {
        const int e = g * 4;
        const int4 r = *reinterpret_cast<const int4*>(rows + e);
        const int prev = (e == 0) ? -1 : __ldg(rows + e - 1);
        if (r.x != prev)
            for (int rr = prev + 1; rr <= r.x; ++rr) g_row_ptr[rr] = e;
        if (r.y != r.x)
            for (int rr = r.x + 1; rr <= r.y; ++rr) g_row_ptr[rr] = e + 1;
        if (r.z != r.y)
            for (int rr = r.y + 1; rr <= r.z; ++rr) g_row_ptr[rr] = e + 2;
        if (r.w != r.z)
            for (int rr = r.z + 1; rr <= r.w; ++rr) g_row_ptr[rr] = e + 3;
    }
    if (tid == 0) {
        // scalar tail (if E not a multiple of 4) + trailing empty rows
        for (int e = ngroups * 4; e < E; ++e) {
            const int pr = (e == 0) ? -1 : __ldg(rows + e - 1);
            const int r = __ldg(rows + e);
            for (int rr = pr + 1; rr <= r; ++rr) g_row_ptr[rr] = e;
        }
        const int last = (E > 0) ? __ldg(rows + E - 1) : -1;
        for (int rr = last + 1; rr <= N_NODES; ++rr) g_row_ptr[rr] = E;
    }
}

// ---------------------------------------------------------------------------
// Kernel 2: h' = h @ W^T, split-bf16 tensor cores, fp16 output.
// ---------------------------------------------------------------------------
#define GEMM_SMEM_BYTES (4 * 128 * 256)  // Ahi, Alo, Whi, Wlo : 32KB each

__device__ __forceinline__ int swz(int row, int col /*bf16 units*/) {
    return row * 256 + (((col * 2) ^ ((row & 7) << 4)));
}
__device__ __forceinline__ uint32_t smem_u32(const void* p) {
    return (uint32_t)__cvta_generic_to_shared(p);
}
__device__ __forceinline__ void ldsm_x4(uint32_t& r0, uint32_t& r1,
                                        uint32_t& r2, uint32_t& r3,
                                        uint32_t addr) {
    asm volatile(
        "ldmatrix.sync.aligned.m8n8.x4.shared.b16 {%0,%1,%2,%3}, [%4];"
        : "=r"(r0), "=r"(r1), "=r"(r2), "=r"(r3)
        : "r"(addr));
}
__device__ __forceinline__ void ldsm_x2(uint32_t& r0, uint32_t& r1,
                                        uint32_t addr) {
    asm volatile(
        "ldmatrix.sync.aligned.m8n8.x2.shared.b16 {%0,%1}, [%2];"
        : "=r"(r0), "=r"(r1)
        : "r"(addr));
}
__device__ __forceinline__ void mma_bf16(float* c, const uint32_t* a,
                                         const uint32_t* b) {
    asm volatile(
        "mma.sync.aligned.m16n8k16.row.col.f32.bf16.bf16.f32 "
        "{%0,%1,%2,%3}, {%4,%5,%6,%7}, {%8,%9}, {%0,%1,%2,%3};"
        : "+f"(c[0]), "+f"(c[1]), "+f"(c[2]), "+f"(c[3])
        : "r"(a[0]), "r"(a[1]), "r"(a[2]), "r"(a[3]), "r"(b[0]), "r"(b[1]));
}
__device__ __forceinline__ uint32_t pack_bf16(float a, float b) {
    __nv_bfloat162 p = __floats2bfloat162_rn(a, b);
    return *reinterpret_cast<uint32_t*>(&p);
}

__global__ __launch_bounds__(256) void transform_tc(
    const float* __restrict__ hin, const float* __restrict__ W) {
    extern __shared__ char smem[];
    char* Ahi_b = smem;
    char* Alo_b = smem + 32768;
    char* Whi_b = smem + 65536;
    char* Wlo_b = smem + 98304;

    const int t = threadIdx.x;
    const int lane = t & 31;
    const int warp = t >> 5;
    const int row0 = blockIdx.x * 128;

#pragma unroll
    for (int i = 0; i < 16; ++i) {
        const int idx = i * 256 + t;
        const int r = idx >> 5;
        const int c4 = idx & 31;
        const int gr = row0 + r;
        float4 a = (gr < N_NODES)
                       ? *reinterpret_cast<const float4*>(hin + (size_t)gr * D + c4 * 4)
                       : make_float4(0.f, 0.f, 0.f, 0.f);
        float h0 = __bfloat162float(__float2bfloat16(a.x));
        float h1 = __bfloat162float(__float2bfloat16(a.y));
        float h2 = __bfloat162float(__float2bfloat16(a.z));
        float h3 = __bfloat162float(__float2bfloat16(a.w));
        const int off = swz(r, c4 * 4);
        *reinterpret_cast<uint2*>(Ahi_b + off) =
            make_uint2(pack_bf16(a.x, a.y), pack_bf16(a.z, a.w));
        *reinterpret_cast<uint2*>(Alo_b + off) =
            make_uint2(pack_bf16(a.x - h0, a.y - h1), pack_bf16(a.z - h2, a.w - h3));
    }
#pragma unroll
    for (int i = 0; i < 16; ++i) {
        const int idx = i * 256 + t;
        const int r = idx >> 5;
        const int c4 = idx & 31;
        float4 a = *reinterpret_cast<const float4*>(W + r * D + c4 * 4);
        float h0 = __bfloat162float(__float2bfloat16(a.x));
        float h1 = __bfloat162float(__float2bfloat16(a.y));
        float h2 = __bfloat162float(__float2bfloat16(a.z));
        float h3 = __bfloat162float(__float2bfloat16(a.w));
        const int off = swz(r, c4 * 4);
        *reinterpret_cast<uint2*>(Whi_b + off) =
            make_uint2(pack_bf16(a.x, a.y), pack_bf16(a.z, a.w));
        *reinterpret_cast<uint2*>(Wlo_b + off) =
            make_uint2(pack_bf16(a.x - h0, a.y - h1), pack_bf16(a.z - h2, a.w - h3));
    }
    __syncthreads();

    const int wm0 = (warp & 3) * 32;
    const int wn0 = (warp >> 2) * 64;

    float c[2][8][4];
#pragma unroll
    for (int mt = 0; mt < 2; ++mt)
#pragma unroll
        for (int nt = 0; nt < 8; ++nt)
#pragma unroll
            for (int k = 0; k < 4; ++k) c[mt][nt][k] = 0.f;

    const uint32_t Ahi_s = smem_u32(Ahi_b);
    const uint32_t Alo_s = smem_u32(Alo_b);
    const uint32_t Whi_s = smem_u32(Whi_b);
    const uint32_t Wlo_s = smem_u32(Wlo_b);

    const int a_row_l = lane & 15;
    const int a_koff = (lane >> 4) * 8;
    const int b_row_l = lane & 7;
    const int b_koff = ((lane >> 3) & 1) * 8;

#pragma unroll
    for (int ks = 0; ks < 8; ++ks) {
        const int k0 = ks * 16;
        uint32_t ahi[2][4], alo[2][4];
#pragma unroll
        for (int mt = 0; mt < 2; ++mt) {
            const int off = swz(wm0 + mt * 16 + a_row_l, k0 + a_koff);
            ldsm_x4(ahi[mt][0], ahi[mt][1], ahi[mt][2], ahi[mt][3], Ahi_s + off);
            ldsm_x4(alo[mt][0], alo[mt][1], alo[mt][2], alo[mt][3], Alo_s + off);
        }
#pragma unroll
        for (int nt = 0; nt < 8; ++nt) {
            const int off = swz(wn0 + nt * 8 + b_row_l, k0 + b_koff);
            uint32_t bhi[2], blo[2];
            ldsm_x2(bhi[0], bhi[1], Whi_s + off);
            ldsm_x2(blo[0], blo[1], Wlo_s + off);
#pragma unroll
            for (int mt = 0; mt < 2; ++mt) {
                mma_bf16(c[mt][nt], ahi[mt], bhi);
                mma_bf16(c[mt][nt], ahi[mt], blo);
                mma_bf16(c[mt][nt], alo[mt], bhi);
            }
        }
    }

    // epilogue: fp16 store
    const int qn = 2 * (lane & 3);
    const int qr = lane >> 2;
#pragma unroll
    for (int mt = 0; mt < 2; ++mt) {
        const int r_lo = row0 + wm0 + mt * 16 + qr;
        const int r_hi = r_lo + 8;
#pragma unroll
        for (int nt = 0; nt < 8; ++nt) {
            const int n = wn0 + nt * 8 + qn;
            if (r_lo < N_NODES)
                *reinterpret_cast<__half2*>(g_ht + (size_t)r_lo * D + n) =
                    __floats2half2_rn(c[mt][nt][0], c[mt][nt][1]);
            if (r_hi < N_NODES)
                *reinterpret_cast<__half2*>(g_ht + (size_t)r_hi * D + n) =
                    __floats2half2_rn(c[mt][nt][2], c[mt][nt][3]);
        }
    }
}

// ---------------------------------------------------------------------------
// Kernel 3: CSR SpMM.  One warp per output row:
//   out[r] = relu( sum_{e in [p0,p1)} vals[e] * h'[cols[e]]  +  b ).
// Inner loop: 4-aligned int4/float4 metadata, 8 independent uint2 gathers
// per iteration (MLP=8), warp-uniform val masking for head/tail overhang.
// No atomics, no branches on row change, one store per row.
// ---------------------------------------------------------------------------
__device__ __forceinline__ void gather_fma(float4& acc, float v, uint2 u) {
    const float2 f01 = __half22float2(*reinterpret_cast<const __half2*>(&u.x));
    const float2 f23 = __half22float2(*reinterpret_cast<const __half2*>(&u.y));
    acc.x = fmaf(v, f01.x, acc.x);
    acc.y = fmaf(v, f01.y, acc.y);
    acc.z = fmaf(v, f23.x, acc.z);
    acc.w = fmaf(v, f23.y, acc.w);
}

__global__ __launch_bounds__(256) void spmm_csr_kernel(
    const int* __restrict__ cols, const float* __restrict__ vals,
    const float* __restrict__ b, float* __restrict__ out) {
    const int warp = (blockIdx.x * blockDim.x + threadIdx.x) >> 5;
    const int lane = threadIdx.x & 31;
    if (warp >= N_NODES) return;
    const int row = warp;

    const int p0 = __ldg(&g_row_ptr[row]);
    const int p1 = __ldg(&g_row_ptr[row + 1]);
    const int fo = lane * 4;
    const float4 bb = *reinterpret_cast<const float4*>(b + fo);
    float* optr = out + (size_t)row * D + fo;

    if (p0 == p1) {  // empty row
        float4 o;
        o.x = fmaxf(bb.x, 0.f);
        o.y = fmaxf(bb.y, 0.f);
        o.z = fmaxf(bb.z, 0.f);
        o.w = fmaxf(bb.w, 0.f);
        *reinterpret_cast<float4*>(optr) = o;
        return;
    }

    float4 a0 = make_float4(0.f, 0.f, 0.f, 0.f);
    float4 a1 = make_float4(0.f, 0.f, 0.f, 0.f);

    int e = p0 & ~3;
    const int p1p = (p1 + 3) & ~3;

    // main loop: 8 edges / iter (two aligned int4 groups)
    for (; e + 8 <= p1p; e += 8) {
        const int4 c0 = *reinterpret_cast<const int4*>(cols + e);
        const int4 c1 = *reinterpret_cast<const int4*>(cols + e + 4);
        float4 v0 = *reinterpret_cast<const float4*>(vals + e);
        float4 v1 = *reinterpret_cast<const float4*>(vals + e + 4);

        // issue all 8 gathers first (independent -> MLP=8)
        const uint2 g0 = *reinterpret_cast<const uint2*>(g_ht + (size_t)c0.x * D + fo);
        const uint2 g1 = *reinterpret_cast<const uint2*>(g_ht + (size_t)c0.y * D + fo);
        const uint2 g2 = *reinterpret_cast<const uint2*>(g_ht + (size_t)c0.z * D + fo);
        const uint2 g3 = *reinterpret_cast<const uint2*>(g_ht + (size_t)c0.w * D + fo);
        const uint2 g4 = *reinterpret_cast<const uint2*>(g_ht + (size_t)c1.x * D + fo);
        const uint2 g5 = *reinterpret_cast<const uint2*>(g_ht + (size_t)c1.y * D + fo);
        const uint2 g6 = *reinterpret_cast<const uint2*>(g_ht + (size_t)c1.z * D + fo);
        const uint2 g7 = *reinterpret_cast<const uint2*>(g_ht + (size_t)c1.w * D + fo);

        // warp-uniform masks for head/tail overhang
        v0.x = (e + 0 >= p0 && e + 0 < p1) ? v0.x : 0.f;
        v0.y = (e + 1 >= p0 && e + 1 < p1) ? v0.y : 0.f;
        v0.z = (e + 2 >= p0 && e + 2 < p1) ? v0.z : 0.f;
        v0.w = (e + 3 >= p0 && e + 3 < p1) ? v0.w : 0.f;
        v1.x = (e + 4 >= p0 && e + 4 < p1) ? v1.x : 0.f;
        v1.y = (e + 5 >= p0 && e + 5 < p1) ? v1.y : 0.f;
        v1.z = (e + 6 >= p0 && e + 6 < p1) ? v1.z : 0.f;
        v1.w = (e + 7 >= p0 && e + 7 < p1) ? v1.w : 0.f;

        gather_fma(a0, v0.x, g0);
        gather_fma(a0, v0.y, g1);
        gather_fma(a0, v0.z, g2);
        gather_fma(a0, v0.w, g3);
        gather_fma(a1, v1.x, g4);
        gather_fma(a1, v1.y, g5);
        gather_fma(a1, v1.z, g6);
        gather_fma(a1, v1.w, g7);
    }
    // final group of 4 (if any)
    if (e < p1p) {
        const int4 c0 = *reinterpret_cast<const int4*>(cols + e);
        float4 v0 = *reinterpret_cast<const float4*>(vals + e);
        const uint2 g0 = *reinterpret_cast<const uint2*>(g_ht + (size_t)c0.x * D + fo);
        const uint2 g1 = *reinterpret_cast<const uint2*>(g_ht + (size_t)c0.y * D + fo);
        const uint2 g2 = *reinterpret_cast<const uint2*>(g_ht + (size_t)c0.z * D + fo);
        const uint2 g3 = *reinterpret_cast<const uint2*>(g_ht + (size_t)c0.w * D + fo);
        v0.x = (e + 0 >= p0 && e + 0 < p1) ? v0.x : 0.f;
        v0.y = (e + 1 >= p0 && e + 1 < p1) ? v0.y : 0.f;
        v0.z = (e + 2 >= p0 && e + 2 < p1) ? v0.z : 0.f;
        v0.w = (e + 3 >= p0 && e + 3 < p1) ? v0.w : 0.f;
        gather_fma(a0, v0.x, g0);
        gather_fma(a0, v0.y, g1);
        gather_fma(a0, v0.z, g2);
        gather_fma(a0, v0.w, g3);
    }

    float4 o;
    o.x = fmaxf(a0.x + a1.x + bb.x, 0.f);
    o.y = fmaxf(a0.y + a1.y + bb.y, 0.f);
    o.z = fmaxf(a0.z + a1.z + bb.z, 0.f);
    o.w = fmaxf(a0.w + a1.w + bb.w, 0.f);
    *reinterpret_cast<float4*>(optr) = o;
}

// ---------------------------------------------------------------------------
// Launch
// ---------------------------------------------------------------------------
extern "C" void kernel_launch(void* const* d_in, const int* in_sizes, int n_in,
                              void* d_out, int out_size) {
    const int* edge_rows = (const int*)d_in[0];
    const int* edge_cols = (const int*)d_in[1];
    const float* edge_vals = (const float*)d_in[2];
    const float* h = (const float*)d_in[3];
    const float* W = (const float*)d_in[4];
    const float* b = (const float*)d_in[5];
    float* out = (float*)d_out;

    const int E = in_sizes[0];

    static bool smem_set = false;
    if (!smem_set) {
        cudaFuncSetAttribute(transform_tc,
                             cudaFuncAttributeMaxDynamicSharedMemorySize,
                             GEMM_SMEM_BYTES);
        smem_set = true;
    }

    // 1) CSR row pointers
    rowptr_build<<<2048, 256>>>(edge_rows, E);

    // 2) h' = h @ W^T  (fp16)
    transform_tc<<<(N_NODES + 127) / 128, 256, GEMM_SMEM_BYTES>>>(h, W);

    // 3) CSR SpMM -> relu(. + b) -> out
    const int sblocks = (N_NODES * 32 + 255) / 256;
    spmm_csr_kernel<<<sblocks, 256>>>(edge_cols, edge_vals, b, out);
}